// round 1
// baseline (speedup 1.0000x reference)
#include <cuda_runtime.h>
#include <cstdint>

// ---------------------------------------------------------------------------
// Problem constants (fixed by the reference)
// ---------------------------------------------------------------------------
#define BB   8
#define LL   2048
#define DD   256
#define DM   1024
#define SS   16
#define NT   (BB * LL)          // 16384 tokens
#define LP1  (LL + 1)           // 2049
#define NROWS (BB * LP1)        // 16392 output rows
#define TOKELEMS (NROWS * DM)   // 16,785,408 floats

// ---------------------------------------------------------------------------
// Device scratch (static: no allocation anywhere)
// ---------------------------------------------------------------------------
__device__ int   g_mask_byte;          // 1 = mask stored as 1-byte bools, 0 = 4-byte words
__device__ int   g_counts[SS];
__device__ int   g_offsets[SS + 1];
__device__ int   g_cursor[SS];
__device__ int   g_tilepfx[SS + 1];
__device__ int   g_total_tiles;
__device__ int   g_tok[NT];
__device__ float g_embg[(size_t)NT * DD];   // gathered emb rows, bucket order (16 MB)

// ---------------------------------------------------------------------------
// Small helpers
// ---------------------------------------------------------------------------
__device__ __forceinline__ bool read_mask(const void* m, int i, int byteMode) {
    if (byteMode) return ((const unsigned char*)m)[i] != 0;
    return ((const unsigned int*)m)[i] != 0u;   // works for int32 {0,1} and float {0,1.0f}
}

__device__ __forceinline__ unsigned long long fma2(unsigned long long a,
                                                   unsigned long long b,
                                                   unsigned long long c) {
    unsigned long long d;
    asm("fma.rn.f32x2 %0, %1, %2, %3;" : "=l"(d) : "l"(a), "l"(b), "l"(c));
    return d;
}
__device__ __forceinline__ unsigned long long dup2(float x) {
    unsigned long long u;
    asm("mov.b64 %0, {%1, %1};" : "=l"(u) : "f"(x));
    return u;
}
__device__ __forceinline__ float2 unpack2(unsigned long long u) {
    float2 f;
    asm("mov.b64 {%0, %1}, %2;" : "=f"(f.x), "=f"(f.y) : "l"(u));
    return f;
}

// ---------------------------------------------------------------------------
// K1: detect mask storage layout + zero counters (1 block)
// ---------------------------------------------------------------------------
__global__ void k_detect(const unsigned int* __restrict__ maskw) {
    __shared__ int bad;
    int tid = threadIdx.x;
    if (tid == 0) bad = 0;
    __syncthreads();
    // Reading 4096 words = 16 KB is safe under either layout (byte buffer is exactly 16 KB).
    int mybad = 0;
    for (int i = tid; i < 4096; i += 256) {
        unsigned int v = maskw[i];
        if (v > 1u && v != 0x3F800000u) mybad = 1;   // not int {0,1} and not float 1.0f
    }
    if (mybad) bad = 1;
    __syncthreads();
    if (tid == 0) g_mask_byte = bad;
    if (tid < SS) g_counts[tid] = 0;
}

// ---------------------------------------------------------------------------
// K2: per-signal counts of masked-in tokens
// ---------------------------------------------------------------------------
__global__ void k_count(const int* __restrict__ sid, const void* __restrict__ mask) {
    __shared__ int scnt[SS];
    int tid = threadIdx.x;
    if (tid < SS) scnt[tid] = 0;
    __syncthreads();
    int byteMode = g_mask_byte;
    int i = blockIdx.x * 256 + tid;
    if (i < NT && read_mask(mask, i, byteMode))
        atomicAdd(&scnt[sid[i]], 1);
    __syncthreads();
    if (tid < SS && scnt[tid]) atomicAdd(&g_counts[tid], scnt[tid]);
}

// ---------------------------------------------------------------------------
// K3: prefix sums + tile prefix (1 thread does 16 values — trivial)
// ---------------------------------------------------------------------------
__global__ void k_prefix() {
    if (threadIdx.x == 0) {
        int off = 0;
        for (int s = 0; s < SS; s++) {
            g_offsets[s] = off;
            g_cursor[s]  = off;
            off += g_counts[s];
        }
        g_offsets[SS] = off;
        int tp = 0;
        for (int s = 0; s < SS; s++) {
            g_tilepfx[s] = tp;
            tp += (g_counts[s] + 63) >> 6;
        }
        g_tilepfx[SS] = tp;
        g_total_tiles = tp * 8;   // 8 N-tiles of 128 over D_MODEL=1024
    }
}

// ---------------------------------------------------------------------------
// K4: scatter token ids into buckets + gather emb rows contiguously
//     one warp per token
// ---------------------------------------------------------------------------
__global__ void k_scatter(const float* __restrict__ emb,
                          const int* __restrict__ sid,
                          const void* __restrict__ mask) {
    int warp = (blockIdx.x * 256 + threadIdx.x) >> 5;
    int lane = threadIdx.x & 31;
    if (warp >= NT) return;
    int t = warp;
    int pos = -1;
    if (lane == 0) {
        if (read_mask(mask, t, g_mask_byte))
            pos = atomicAdd(&g_cursor[sid[t]], 1);
    }
    pos = __shfl_sync(0xFFFFFFFFu, pos, 0);
    if (pos < 0) return;
    if (lane == 0) g_tok[pos] = t;
    const float4* src = (const float4*)(emb + (size_t)t * DD);
    float4* dst = (float4*)(g_embg + (size_t)pos * DD);
    dst[lane]      = src[lane];
    dst[lane + 32] = src[lane + 32];
}

// ---------------------------------------------------------------------------
// K5: base output = embeddings (+CLS content on row 0), plus attn_keep
//     one block per output row, 256 threads x float4 = 1024 floats
// ---------------------------------------------------------------------------
__global__ void k_base(const int* __restrict__ pos,
                       const int* __restrict__ sid,
                       const int* __restrict__ role,
                       const void* __restrict__ mask,
                       const float* __restrict__ clsc,
                       const float* __restrict__ pe,
                       const float* __restrict__ ide,
                       const float* __restrict__ re,
                       float* __restrict__ out,
                       int attnMode) {
    int r = blockIdx.x;               // 0 .. NROWS-1
    int b = r / LP1;
    int l = r - b * LP1;
    int j = threadIdx.x;              // float4 index 0..255

    const float4* pe4  = (const float4*)pe;
    const float4* ide4 = (const float4*)ide;
    const float4* re4  = (const float4*)re;

    float4 v;
    if (l == 0) {
        float4 c  = ((const float4*)clsc)[j];
        float4 p  = pe4[j];                    // pos 0
        float4 id = ide4[(size_t)SS * 256 + j];  // cls_id = 16
        float4 ro = re4[(size_t)2 * 256 + j];    // ROLE_OUTPUT = 2
        v.x = c.x + p.x + id.x + ro.x;
        v.y = c.y + p.y + id.y + ro.y;
        v.z = c.z + p.z + id.z + ro.z;
        v.w = c.w + p.w + id.w + ro.w;
    } else {
        int t  = b * LL + (l - 1);
        int p  = pos[t];
        int s  = sid[t];
        int ro = role[t];
        float4 pv  = pe4[(size_t)p * 256 + j];
        float4 iv  = ide4[(size_t)s * 256 + j];
        float4 rv  = re4[(size_t)ro * 256 + j];
        v.x = pv.x + iv.x + rv.x;
        v.y = pv.y + iv.y + rv.y;
        v.z = pv.z + iv.z + rv.z;
        v.w = pv.w + iv.w + rv.w;
    }
    ((float4*)out)[(size_t)r * 256 + j] = v;

    if (threadIdx.x == 0 && attnMode != 0) {
        bool keep = (l == 0) ? true : read_mask(mask, b * LL + (l - 1), g_mask_byte);
        if (attnMode == 1)
            out[(size_t)TOKELEMS + r] = keep ? 1.0f : 0.0f;
        else
            ((unsigned char*)(out + TOKELEMS))[r] = keep ? 1 : 0;
    }
}

// ---------------------------------------------------------------------------
// K6: grouped GEMM (persistent CTAs), fp32 via packed fma.rn.f32x2
//     Tile: BM=64 tokens x BN=128 d_model x BK=16, 256 threads, 4x8 per thread
//     Epilogue: out[tokenrow, cols] += acc + proj_b[s]
// ---------------------------------------------------------------------------
__global__ __launch_bounds__(256) void k_gemm(const float* __restrict__ W,
                                              const float* __restrict__ bias,
                                              float* __restrict__ out) {
    __shared__ __align__(16) float As[16][68];
    __shared__ __align__(16) float Bs[16][132];
    __shared__ int sTile[SS + 1], sCnt[SS], sOff[SS];

    int tid = threadIdx.x;
    if (tid <= SS) sTile[tid] = g_tilepfx[tid];
    if (tid < SS) { sCnt[tid] = g_counts[tid]; sOff[tid] = g_offsets[tid]; }
    __syncthreads();
    int total = g_total_tiles;

    int ty = tid >> 4, tx = tid & 15;
    int rm = ty * 4;          // M sub-tile base (0..60)
    int cn = tx * 8;          // N sub-tile base (0..120)
    int arow = tid >> 2;      // load row (0..63)
    int ak   = (tid & 3) * 4; // load k base

    for (int t = blockIdx.x; t < total; t += gridDim.x) {
        int nt  = t & 7;
        int mtl = t >> 3;
        int s = 0;
        while (sTile[s + 1] <= mtl) s++;
        int mt   = mtl - sTile[s];
        int cnt  = sCnt[s];
        int base = sOff[s];
        int m0   = mt * 64;
        int rows = cnt - m0; if (rows > 64) rows = 64;

        const float* Ap = g_embg + (size_t)(base + m0) * DD;
        const float* Wp = W + ((size_t)s * DM + (size_t)nt * 128) * DD;

        unsigned long long acc[4][4];
        #pragma unroll
        for (int i = 0; i < 4; i++)
            #pragma unroll
            for (int j = 0; j < 4; j++) acc[i][j] = 0ULL;

        #pragma unroll 1
        for (int kt = 0; kt < DD / 16; kt++) {
            float4 av = make_float4(0.f, 0.f, 0.f, 0.f);
            if (arow < rows)
                av = *(const float4*)(Ap + (size_t)arow * DD + kt * 16 + ak);
            float4 wv0 = *(const float4*)(Wp + (size_t)arow * DD + kt * 16 + ak);
            float4 wv1 = *(const float4*)(Wp + (size_t)(arow + 64) * DD + kt * 16 + ak);

            __syncthreads();
            As[ak + 0][arow] = av.x;  As[ak + 1][arow] = av.y;
            As[ak + 2][arow] = av.z;  As[ak + 3][arow] = av.w;
            Bs[ak + 0][arow] = wv0.x; Bs[ak + 1][arow] = wv0.y;
            Bs[ak + 2][arow] = wv0.z; Bs[ak + 3][arow] = wv0.w;
            Bs[ak + 0][arow + 64] = wv1.x; Bs[ak + 1][arow + 64] = wv1.y;
            Bs[ak + 2][arow + 64] = wv1.z; Bs[ak + 3][arow + 64] = wv1.w;
            __syncthreads();

            #pragma unroll
            for (int k = 0; k < 16; k++) {
                float4 a = *(const float4*)&As[k][rm];
                unsigned long long pa0 = dup2(a.x);
                unsigned long long pa1 = dup2(a.y);
                unsigned long long pa2 = dup2(a.z);
                unsigned long long pa3 = dup2(a.w);
                ulonglong2 bA = *(const ulonglong2*)&Bs[k][cn];
                ulonglong2 bB = *(const ulonglong2*)&Bs[k][cn + 4];
                acc[0][0] = fma2(pa0, bA.x, acc[0][0]);
                acc[0][1] = fma2(pa0, bA.y, acc[0][1]);
                acc[0][2] = fma2(pa0, bB.x, acc[0][2]);
                acc[0][3] = fma2(pa0, bB.y, acc[0][3]);
                acc[1][0] = fma2(pa1, bA.x, acc[1][0]);
                acc[1][1] = fma2(pa1, bA.y, acc[1][1]);
                acc[1][2] = fma2(pa1, bB.x, acc[1][2]);
                acc[1][3] = fma2(pa1, bB.y, acc[1][3]);
                acc[2][0] = fma2(pa2, bA.x, acc[2][0]);
                acc[2][1] = fma2(pa2, bA.y, acc[2][1]);
                acc[2][2] = fma2(pa2, bB.x, acc[2][2]);
                acc[2][3] = fma2(pa2, bB.y, acc[2][3]);
                acc[3][0] = fma2(pa3, bA.x, acc[3][0]);
                acc[3][1] = fma2(pa3, bA.y, acc[3][1]);
                acc[3][2] = fma2(pa3, bB.x, acc[3][2]);
                acc[3][3] = fma2(pa3, bB.y, acc[3][3]);
            }
        }

        // Epilogue: scatter-accumulate into base output rows (+bias)
        const float* bp = bias + (size_t)s * DM + nt * 128 + cn;
        float4 b0 = *(const float4*)bp;
        float4 b1 = *(const float4*)(bp + 4);
        #pragma unroll
        for (int i = 0; i < 4; i++) {
            int r = rm + i;
            if (r < rows) {
                int tok  = g_tok[base + m0 + r];
                int orow = tok + (tok >> 11) + 1;   // (b, l) -> (b, l+1) with L=2048
                float* op = out + (size_t)orow * DM + nt * 128 + cn;
                float4 o0 = *(float4*)op;
                float4 o1 = *(float4*)(op + 4);
                float2 v;
                v = unpack2(acc[i][0]); o0.x += v.x + b0.x; o0.y += v.y + b0.y;
                v = unpack2(acc[i][1]); o0.z += v.x + b0.z; o0.w += v.y + b0.w;
                v = unpack2(acc[i][2]); o1.x += v.x + b1.x; o1.y += v.y + b1.y;
                v = unpack2(acc[i][3]); o1.z += v.x + b1.z; o1.w += v.y + b1.w;
                *(float4*)op       = o0;
                *(float4*)(op + 4) = o1;
            }
        }
    }
}

// ---------------------------------------------------------------------------
// kernel_launch
//   inputs (metadata order = setup_inputs dict order):
//   0 emb (8,2048,256) f32 | 1 pos i32 | 2 sid i32 | 3 role i32 | 4 padding_mask
//   5 proj_W (16,1024,256) f32 | 6 proj_b (16,1024) f32 | 7 cls_content (1024) f32
//   8 pos_embed (4097,1024) f32 | 9 id_embed (17,1024) f32 | 10 role_embed (3,1024) f32
// ---------------------------------------------------------------------------
extern "C" void kernel_launch(void* const* d_in, const int* in_sizes, int n_in,
                              void* d_out, int out_size) {
    const float* emb  = (const float*)d_in[0];
    const int*   pos  = (const int*)d_in[1];
    const int*   sid  = (const int*)d_in[2];
    const int*   role = (const int*)d_in[3];
    const void*  mask = d_in[4];
    const float* pW   = (const float*)d_in[5];
    const float* pb   = (const float*)d_in[6];
    const float* clsc = (const float*)d_in[7];
    const float* pe   = (const float*)d_in[8];
    const float* ide  = (const float*)d_in[9];
    const float* re   = (const float*)d_in[10];
    float* out = (float*)d_out;

    // Does the output buffer also carry attn_keep? (robust to harness layout)
    int extra = out_size - TOKELEMS;
    int attnMode = 0;
    if (extra >= NROWS)           attnMode = 1;   // float 0/1 appended
    else if (extra >= (NROWS + 3) / 4) attnMode = 2;   // byte 0/1 appended

    k_detect <<<1, 256>>>((const unsigned int*)mask);
    k_count  <<<NT / 256, 256>>>(sid, mask);
    k_prefix <<<1, 32>>>();
    k_scatter<<<NT / 8, 256>>>(emb, sid, mask);
    k_base   <<<NROWS, 256>>>(pos, sid, role, mask, clsc, pe, ide, re, out, attnMode);
    k_gemm   <<<448, 256>>>(pW, pb, out);
}

// round 5
// speedup vs baseline: 1.4146x; 1.4146x over previous
#include <cuda_runtime.h>
#include <cstdint>

// ---------------------------------------------------------------------------
// Problem constants
// ---------------------------------------------------------------------------
#define BB   8
#define LL   2048
#define DD   256
#define DM   1024
#define SS   16
#define NT   (BB * LL)          // 16384 tokens
#define LP1  (LL + 1)
#define NROWS (BB * LP1)        // 16392 output rows
#define TOKELEMS (NROWS * DM)

// ---------------------------------------------------------------------------
// Device scratch (no allocation anywhere)
// ---------------------------------------------------------------------------
__device__ int g_mask_byte;
__device__ int g_counts[SS];
__device__ int g_offsets[SS + 1];
__device__ int g_cursor[SS];
__device__ int g_tilepfx[SS + 1];
__device__ int g_total_tiles;
__device__ int g_tok[NT + 256];

// ---------------------------------------------------------------------------
// Helpers
// ---------------------------------------------------------------------------
__device__ __forceinline__ bool read_mask(const void* m, int i, int byteMode) {
    if (byteMode) return ((const unsigned char*)m)[i] != 0;
    return ((const unsigned int*)m)[i] != 0u;
}
__device__ __forceinline__ unsigned long long fma2(unsigned long long a,
                                                   unsigned long long b,
                                                   unsigned long long c) {
    unsigned long long d;
    asm("fma.rn.f32x2 %0, %1, %2, %3;" : "=l"(d) : "l"(a), "l"(b), "l"(c));
    return d;
}
__device__ __forceinline__ unsigned long long dup2(float x) {
    unsigned long long u;
    asm("mov.b64 %0, {%1, %1};" : "=l"(u) : "f"(x));
    return u;
}
__device__ __forceinline__ float2 unpack2(unsigned long long u) {
    float2 f;
    asm("mov.b64 {%0, %1}, %2;" : "=f"(f.x), "=f"(f.y) : "l"(u));
    return f;
}

// ---------------------------------------------------------------------------
// K1: detect mask storage layout + zero counters
// ---------------------------------------------------------------------------
__global__ void k_detect(const unsigned int* __restrict__ maskw) {
    __shared__ int bad;
    int tid = threadIdx.x;
    if (tid == 0) bad = 0;
    __syncthreads();
    int mybad = 0;
    for (int i = tid; i < 4096; i += 256) {
        unsigned int v = maskw[i];
        if (v > 1u && v != 0x3F800000u) mybad = 1;
    }
    if (mybad) bad = 1;
    __syncthreads();
    if (tid == 0) g_mask_byte = bad;
    if (tid < SS) g_counts[tid] = 0;
}

// ---------------------------------------------------------------------------
// K2: per-signal counts
// ---------------------------------------------------------------------------
__global__ void k_count(const int* __restrict__ sid, const void* __restrict__ mask) {
    __shared__ int scnt[SS];
    int tid = threadIdx.x;
    if (tid < SS) scnt[tid] = 0;
    __syncthreads();
    int i = blockIdx.x * 256 + tid;
    if (i < NT && read_mask(mask, i, g_mask_byte))
        atomicAdd(&scnt[sid[i]], 1);
    __syncthreads();
    if (tid < SS && scnt[tid]) atomicAdd(&g_counts[tid], scnt[tid]);
}

// ---------------------------------------------------------------------------
// K3: prefix sums + tile prefix (M-tiles of 128)
// ---------------------------------------------------------------------------
__global__ void k_prefix() {
    if (threadIdx.x == 0) {
        int off = 0;
        for (int s = 0; s < SS; s++) {
            g_offsets[s] = off;
            g_cursor[s]  = off;
            off += g_counts[s];
        }
        g_offsets[SS] = off;
        int tp = 0;
        for (int s = 0; s < SS; s++) {
            g_tilepfx[s] = tp;
            tp += (g_counts[s] + 127) >> 7;
        }
        g_tilepfx[SS] = tp;
        g_total_tiles = tp * 8;   // 8 N-tiles of 128 over D_MODEL
    }
}

// ---------------------------------------------------------------------------
// K4: bucket ranks only (block-aggregated atomics); no data copy
// ---------------------------------------------------------------------------
__global__ void k_scatter(const int* __restrict__ sid, const void* __restrict__ mask) {
    __shared__ int cnt[SS], bb[SS];
    int tid = threadIdx.x;
    int t = blockIdx.x * 256 + tid;
    if (tid < SS) cnt[tid] = 0;
    __syncthreads();
    int s = -1, rk = 0;
    if (t < NT && read_mask(mask, t, g_mask_byte)) {
        s = sid[t];
        rk = atomicAdd(&cnt[s], 1);
    }
    __syncthreads();
    if (tid < SS) bb[tid] = cnt[tid] ? atomicAdd(&g_cursor[tid], cnt[tid]) : 0;
    __syncthreads();
    if (s >= 0) g_tok[bb[s] + rk] = t;
}

// ---------------------------------------------------------------------------
// K5: base rows (CLS + masked-out tokens only) + attn_keep output
// ---------------------------------------------------------------------------
__global__ void k_base(const int* __restrict__ pos,
                       const int* __restrict__ sid,
                       const int* __restrict__ role,
                       const void* __restrict__ mask,
                       const float* __restrict__ clsc,
                       const float* __restrict__ pe,
                       const float* __restrict__ ide,
                       const float* __restrict__ re,
                       float* __restrict__ out,
                       int attnMode) {
    int r = blockIdx.x;
    int b = r / LP1;
    int l = r - b * LP1;
    int j = threadIdx.x;                 // float4 index 0..255
    int t = b * LL + (l - 1);
    bool keep = (l == 0) ? true : read_mask(mask, t, g_mask_byte);

    if (j == 0 && attnMode != 0) {
        if (attnMode == 1)
            out[(size_t)TOKELEMS + r] = keep ? 1.0f : 0.0f;
        else
            ((unsigned char*)(out + TOKELEMS))[r] = keep ? 1 : 0;
    }
    if (l > 0 && keep) return;           // projected rows are written by k_gemm

    const float4* pe4  = (const float4*)pe;
    const float4* ide4 = (const float4*)ide;
    const float4* re4  = (const float4*)re;
    float4 v;
    if (l == 0) {
        float4 c  = ((const float4*)clsc)[j];
        float4 p  = pe4[j];
        float4 id = ide4[(size_t)SS * 256 + j];
        float4 ro = re4[(size_t)2 * 256 + j];
        v.x = c.x + p.x + id.x + ro.x;
        v.y = c.y + p.y + id.y + ro.y;
        v.z = c.z + p.z + id.z + ro.z;
        v.w = c.w + p.w + id.w + ro.w;
    } else {
        float4 pv = pe4[(size_t)pos[t] * 256 + j];
        float4 iv = ide4[(size_t)sid[t] * 256 + j];
        float4 rv = re4[(size_t)role[t] * 256 + j];
        v.x = pv.x + iv.x + rv.x;
        v.y = pv.y + iv.y + rv.y;
        v.z = pv.z + iv.z + rv.z;
        v.w = pv.w + iv.w + rv.w;
    }
    ((float4*)out)[(size_t)r * 256 + j] = v;
}

// ---------------------------------------------------------------------------
// K6: grouped GEMM, BM=128 BN=128 BK=16, double-buffered, f32x2 FMA,
//     fused epilogue (bias + pos/id/role embeds), direct final store.
// ---------------------------------------------------------------------------
__global__ __launch_bounds__(256, 2) void k_gemm(
    const float* __restrict__ emb,
    const int* __restrict__ pos,
    const int* __restrict__ sid,
    const int* __restrict__ role,
    const float* __restrict__ W,
    const float* __restrict__ bias,
    const float* __restrict__ pe,
    const float* __restrict__ ide,
    const float* __restrict__ re,
    float* __restrict__ out) {

    __shared__ __align__(16) float As[2][16][132];
    __shared__ __align__(16) float Bs[2][16][132];
    __shared__ int sTok[128], sPos[128], sSid[128], sRole[128];
    __shared__ int sTile[SS + 1], sCnt[SS], sOff[SS];

    int tid = threadIdx.x;
    if (tid <= SS) sTile[tid] = g_tilepfx[tid];
    if (tid < SS) { sCnt[tid] = g_counts[tid]; sOff[tid] = g_offsets[tid]; }
    __syncthreads();
    int total = g_total_tiles;

    // 4x8 warp shape: ty in 0..15 (8 rows each), tx in 0..15 (8 cols each)
    int lane = tid & 31, w = tid >> 5;
    int ty = ((w >> 1) << 2) | (lane >> 3);
    int tx = ((w & 1) << 3) | (lane & 7);
    int rm = ty * 8, cn = tx * 8;
    int lrow = tid >> 1, lk = (tid & 1) * 8;

    for (int t = blockIdx.x; t < total; t += gridDim.x) {
        int nt = t & 7, mtl = t >> 3;
        int s = 0;
        while (sTile[s + 1] <= mtl) s++;
        int base = sOff[s];
        int m0 = (mtl - sTile[s]) << 7;
        int rows = sCnt[s] - m0; if (rows > 128) rows = 128;

        __syncthreads();                 // sTok reuse vs previous tile epilogue
        if (tid < 128) {
            int tk = (tid < rows) ? g_tok[base + m0 + tid] : 0;
            sTok[tid] = tk;
            sPos[tid] = pos[tk];
            sSid[tid] = sid[tk];
            sRole[tid] = role[tk];
        }
        __syncthreads();

        const float* Ap = emb + (size_t)sTok[lrow] * DD + lk;
        const float* Bp = W + ((size_t)s * DM + (size_t)nt * 128 + lrow) * DD + lk;

        float4 ra0 = *(const float4*)(Ap);
        float4 ra1 = *(const float4*)(Ap + 4);
        float4 rb0 = *(const float4*)(Bp);
        float4 rb1 = *(const float4*)(Bp + 4);
        {
            float* a = &As[0][lk][lrow];
            a[0] = ra0.x; a[132] = ra0.y; a[264] = ra0.z; a[396] = ra0.w;
            a[528] = ra1.x; a[660] = ra1.y; a[792] = ra1.z; a[924] = ra1.w;
            float* b = &Bs[0][lk][lrow];
            b[0] = rb0.x; b[132] = rb0.y; b[264] = rb0.z; b[396] = rb0.w;
            b[528] = rb1.x; b[660] = rb1.y; b[792] = rb1.z; b[924] = rb1.w;
        }
        __syncthreads();

        unsigned long long acc[4][8];
        #pragma unroll
        for (int i = 0; i < 4; i++)
            #pragma unroll
            for (int j = 0; j < 8; j++) acc[i][j] = 0ULL;

        #pragma unroll 1
        for (int kt = 0; kt < 16; kt++) {
            if (kt < 15) {
                const float* A2 = Ap + (kt + 1) * 16;
                const float* B2 = Bp + (kt + 1) * 16;
                ra0 = *(const float4*)(A2);
                ra1 = *(const float4*)(A2 + 4);
                rb0 = *(const float4*)(B2);
                rb1 = *(const float4*)(B2 + 4);
            }
            const float (*Ab)[132] = As[kt & 1];
            const float (*Bb)[132] = Bs[kt & 1];
            #pragma unroll
            for (int k = 0; k < 16; k++) {
                ulonglong2 aP = *(const ulonglong2*)&Ab[k][rm];     // rows rm..rm+3
                ulonglong2 aQ = *(const ulonglong2*)&Ab[k][rm + 4]; // rows rm+4..rm+7
                float4 b0 = *(const float4*)&Bb[k][cn];
                float4 b1 = *(const float4*)&Bb[k][cn + 4];
                unsigned long long pb;
                pb = dup2(b0.x);
                acc[0][0] = fma2(aP.x, pb, acc[0][0]);
                acc[1][0] = fma2(aP.y, pb, acc[1][0]);
                acc[2][0] = fma2(aQ.x, pb, acc[2][0]);
                acc[3][0] = fma2(aQ.y, pb, acc[3][0]);
                pb = dup2(b0.y);
                acc[0][1] = fma2(aP.x, pb, acc[0][1]);
                acc[1][1] = fma2(aP.y, pb, acc[1][1]);
                acc[2][1] = fma2(aQ.x, pb, acc[2][1]);
                acc[3][1] = fma2(aQ.y, pb, acc[3][1]);
                pb = dup2(b0.z);
                acc[0][2] = fma2(aP.x, pb, acc[0][2]);
                acc[1][2] = fma2(aP.y, pb, acc[1][2]);
                acc[2][2] = fma2(aQ.x, pb, acc[2][2]);
                acc[3][2] = fma2(aQ.y, pb, acc[3][2]);
                pb = dup2(b0.w);
                acc[0][3] = fma2(aP.x, pb, acc[0][3]);
                acc[1][3] = fma2(aP.y, pb, acc[1][3]);
                acc[2][3] = fma2(aQ.x, pb, acc[2][3]);
                acc[3][3] = fma2(aQ.y, pb, acc[3][3]);
                pb = dup2(b1.x);
                acc[0][4] = fma2(aP.x, pb, acc[0][4]);
                acc[1][4] = fma2(aP.y, pb, acc[1][4]);
                acc[2][4] = fma2(aQ.x, pb, acc[2][4]);
                acc[3][4] = fma2(aQ.y, pb, acc[3][4]);
                pb = dup2(b1.y);
                acc[0][5] = fma2(aP.x, pb, acc[0][5]);
                acc[1][5] = fma2(aP.y, pb, acc[1][5]);
                acc[2][5] = fma2(aQ.x, pb, acc[2][5]);
                acc[3][5] = fma2(aQ.y, pb, acc[3][5]);
                pb = dup2(b1.z);
                acc[0][6] = fma2(aP.x, pb, acc[0][6]);
                acc[1][6] = fma2(aP.y, pb, acc[1][6]);
                acc[2][6] = fma2(aQ.x, pb, acc[2][6]);
                acc[3][6] = fma2(aQ.y, pb, acc[3][6]);
                pb = dup2(b1.w);
                acc[0][7] = fma2(aP.x, pb, acc[0][7]);
                acc[1][7] = fma2(aP.y, pb, acc[1][7]);
                acc[2][7] = fma2(aQ.x, pb, acc[2][7]);
                acc[3][7] = fma2(aQ.y, pb, acc[3][7]);
            }
            if (kt < 15) {
                float* a = &As[(kt + 1) & 1][lk][lrow];
                a[0] = ra0.x; a[132] = ra0.y; a[264] = ra0.z; a[396] = ra0.w;
                a[528] = ra1.x; a[660] = ra1.y; a[792] = ra1.z; a[924] = ra1.w;
                float* b = &Bs[(kt + 1) & 1][lk][lrow];
                b[0] = rb0.x; b[132] = rb0.y; b[264] = rb0.z; b[396] = rb0.w;
                b[528] = rb1.x; b[660] = rb1.y; b[792] = rb1.z; b[924] = rb1.w;
                __syncthreads();
            }
        }

        // Fused epilogue: out = acc + bias + pe[pos] + ide[sid] + re[role]
        const float* bp = bias + (size_t)s * DM + (size_t)nt * 128 + cn;
        float4 bb0 = *(const float4*)(bp);
        float4 bb1 = *(const float4*)(bp + 4);
        size_t colbase = (size_t)nt * 32 + (size_t)tx * 2;   // float4 units

        #pragma unroll
        for (int i2 = 0; i2 < 4; i2++) {
            float2 c0 = unpack2(acc[i2][0]);
            float2 c1 = unpack2(acc[i2][1]);
            float2 c2 = unpack2(acc[i2][2]);
            float2 c3 = unpack2(acc[i2][3]);
            float2 c4 = unpack2(acc[i2][4]);
            float2 c5 = unpack2(acc[i2][5]);
            float2 c6 = unpack2(acc[i2][6]);
            float2 c7 = unpack2(acc[i2][7]);
            #pragma unroll
            for (int h = 0; h < 2; h++) {
                int r = rm + i2 * 2 + h;
                if (r >= rows) continue;
                int tok = sTok[r];
                int orow = tok + (tok >> 11) + 1;   // (b,l) -> row b*(L+1)+l+1
                const float4* p4 = (const float4*)pe  + (size_t)sPos[r] * 256 + colbase;
                const float4* i4 = (const float4*)ide + (size_t)sSid[r] * 256 + colbase;
                const float4* r4 = (const float4*)re  + (size_t)sRole[r] * 256 + colbase;
                float4 pa = p4[0], pb_ = p4[1];
                float4 ia = i4[0], ib  = i4[1];
                float4 ra = r4[0], rb  = r4[1];
                float4 o0, o1;
                o0.x = (h ? c0.y : c0.x) + bb0.x + pa.x + ia.x + ra.x;
                o0.y = (h ? c1.y : c1.x) + bb0.y + pa.y + ia.y + ra.y;
                o0.z = (h ? c2.y : c2.x) + bb0.z + pa.z + ia.z + ra.z;
                o0.w = (h ? c3.y : c3.x) + bb0.w + pa.w + ia.w + ra.w;
                o1.x = (h ? c4.y : c4.x) + bb1.x + pb_.x + ib.x + rb.x;
                o1.y = (h ? c5.y : c5.x) + bb1.y + pb_.y + ib.y + rb.y;
                o1.z = (h ? c6.y : c6.x) + bb1.z + pb_.z + ib.z + rb.z;
                o1.w = (h ? c7.y : c7.x) + bb1.w + pb_.w + ib.w + rb.w;
                float4* op = (float4*)out + (size_t)orow * 256 + colbase;
                op[0] = o0;
                op[1] = o1;
            }
        }
    }
}

// ---------------------------------------------------------------------------
// kernel_launch
// ---------------------------------------------------------------------------
extern "C" void kernel_launch(void* const* d_in, const int* in_sizes, int n_in,
                              void* d_out, int out_size) {
    const float* emb  = (const float*)d_in[0];
    const int*   pos  = (const int*)d_in[1];
    const int*   sid  = (const int*)d_in[2];
    const int*   role = (const int*)d_in[3];
    const void*  mask = d_in[4];
    const float* pW   = (const float*)d_in[5];
    const float* pb   = (const float*)d_in[6];
    const float* clsc = (const float*)d_in[7];
    const float* pe   = (const float*)d_in[8];
    const float* ide  = (const float*)d_in[9];
    const float* re   = (const float*)d_in[10];
    float* out = (float*)d_out;

    int extra = out_size - TOKELEMS;
    int attnMode = 0;
    if (extra >= NROWS)                attnMode = 1;
    else if (extra >= (NROWS + 3) / 4) attnMode = 2;

    k_detect <<<1, 256>>>((const unsigned int*)mask);
    k_count  <<<NT / 256, 256>>>(sid, mask);
    k_prefix <<<1, 32>>>();
    k_scatter<<<NT / 256, 256>>>(sid, mask);
    k_base   <<<NROWS, 256>>>(pos, sid, role, mask, clsc, pe, ide, re, out, attnMode);
    k_gemm   <<<296, 256>>>(emb, pos, sid, role, pW, pb, pe, ide, re, out);
}

// round 8
// speedup vs baseline: 1.9987x; 1.4129x over previous
#include <cuda_runtime.h>
#include <cuda_fp16.h>
#include <mma.h>
#include <cstdint>

using namespace nvcuda;

// ---------------------------------------------------------------------------
// Problem constants
// ---------------------------------------------------------------------------
#define BB   8
#define LL   2048
#define DD   256
#define DM   1024
#define SS   16
#define NT   (BB * LL)
#define LP1  (LL + 1)
#define NROWS (BB * LP1)
#define TOKELEMS (NROWS * DM)

// GEMM tiling
#define BK        32           // fp32 K elements per chunk
#define NCHUNK    (DD / BK)    // 8
#define LDH       40           // halves per row in smem (pad for ldmatrix)
#define MATH      (128 * LDH)  // halves per matrix tile (5120)
#define STAGEH    (4 * MATH)   // halves per stage (Ahi,Alo,Bhi,Blo) = 20480
#define EPILD     72           // epilogue smem leading dim (floats)
#define DYN_SMEM  (2 * STAGEH * 2)   // bytes = 81920

// ---------------------------------------------------------------------------
// Device scratch
// ---------------------------------------------------------------------------
__device__ int g_mask_byte;
__device__ int g_cursor[SS];
__device__ int g_tok[SS * NT];

__device__ __forceinline__ bool read_mask(const void* m, int i, int byteMode) {
    if (byteMode) return ((const unsigned char*)m)[i] != 0;
    return ((const unsigned int*)m)[i] != 0u;
}

// ---------------------------------------------------------------------------
// K1: mask layout detect + zero cursors
// ---------------------------------------------------------------------------
__global__ void k_detect(const unsigned int* __restrict__ maskw) {
    __shared__ int bad;
    int tid = threadIdx.x;
    if (tid == 0) bad = 0;
    __syncthreads();
    int mybad = 0;
    for (int i = tid; i < 4096; i += 256) {
        unsigned int v = maskw[i];
        if (v > 1u && v != 0x3F800000u) mybad = 1;
    }
    if (mybad) bad = 1;
    __syncthreads();
    if (tid == 0) g_mask_byte = bad;
    if (tid < SS) g_cursor[tid] = 0;
}

// ---------------------------------------------------------------------------
// K2: bucket tokens into per-signal private regions
// ---------------------------------------------------------------------------
__global__ void k_scatter(const int* __restrict__ sid, const void* __restrict__ mask) {
    __shared__ int cnt[SS], bb[SS];
    int tid = threadIdx.x;
    int t = blockIdx.x * 256 + tid;
    if (tid < SS) cnt[tid] = 0;
    __syncthreads();
    int s = -1, rk = 0;
    if (t < NT && read_mask(mask, t, g_mask_byte)) {
        s = sid[t];
        rk = atomicAdd(&cnt[s], 1);
    }
    __syncthreads();
    if (tid < SS) bb[tid] = cnt[tid] ? atomicAdd(&g_cursor[tid], cnt[tid]) : 0;
    __syncthreads();
    if (s >= 0) g_tok[s * NT + bb[s] + rk] = t;
}

// ---------------------------------------------------------------------------
// K3: base rows (CLS + masked-out) + attn_keep
// ---------------------------------------------------------------------------
__global__ void k_base(const int* __restrict__ pos, const int* __restrict__ sid,
                       const int* __restrict__ role, const void* __restrict__ mask,
                       const float* __restrict__ clsc, const float* __restrict__ pe,
                       const float* __restrict__ ide, const float* __restrict__ re,
                       float* __restrict__ out, int attnMode) {
    int r = blockIdx.x;
    int b = r / LP1;
    int l = r - b * LP1;
    int j = threadIdx.x;
    int t = b * LL + (l - 1);
    bool keep = (l == 0) ? true : read_mask(mask, t, g_mask_byte);

    if (j == 0 && attnMode != 0) {
        if (attnMode == 1) out[(size_t)TOKELEMS + r] = keep ? 1.0f : 0.0f;
        else ((unsigned char*)(out + TOKELEMS))[r] = keep ? 1 : 0;
    }
    if (l > 0 && keep) return;

    const float4* pe4  = (const float4*)pe;
    const float4* ide4 = (const float4*)ide;
    const float4* re4  = (const float4*)re;
    float4 v;
    if (l == 0) {
        float4 c  = ((const float4*)clsc)[j];
        float4 p  = pe4[j];
        float4 id = ide4[(size_t)SS * 256 + j];
        float4 ro = re4[(size_t)2 * 256 + j];
        v.x = c.x + p.x + id.x + ro.x; v.y = c.y + p.y + id.y + ro.y;
        v.z = c.z + p.z + id.z + ro.z; v.w = c.w + p.w + id.w + ro.w;
    } else {
        float4 pv = pe4[(size_t)pos[t] * 256 + j];
        float4 iv = ide4[(size_t)sid[t] * 256 + j];
        float4 rv = re4[(size_t)role[t] * 256 + j];
        v.x = pv.x + iv.x + rv.x; v.y = pv.y + iv.y + rv.y;
        v.z = pv.z + iv.z + rv.z; v.w = pv.w + iv.w + rv.w;
    }
    ((float4*)out)[(size_t)r * 256 + j] = v;
}

// ---------------------------------------------------------------------------
// fp16 hi/lo split store (4 fp32 -> 4 hi halves + 4 lo halves)
// ---------------------------------------------------------------------------
__device__ __forceinline__ void split4(float4 v, half* hp, half* lp) {
    half h0 = __float2half_rn(v.x); half l0 = __float2half_rn(v.x - __half2float(h0));
    half h1 = __float2half_rn(v.y); half l1 = __float2half_rn(v.y - __half2float(h1));
    half h2 = __float2half_rn(v.z); half l2 = __float2half_rn(v.z - __half2float(h2));
    half h3 = __float2half_rn(v.w); half l3 = __float2half_rn(v.w - __half2float(h3));
    *(half2*)(hp)     = __halves2half2(h0, h1);
    *(half2*)(hp + 2) = __halves2half2(h2, h3);
    *(half2*)(lp)     = __halves2half2(l0, l1);
    *(half2*)(lp + 2) = __halves2half2(l2, l3);
}

// ---------------------------------------------------------------------------
// K4: grouped GEMM via wmma (HMMA), 3xFP16 split, fused epilogue
// ---------------------------------------------------------------------------
__global__ __launch_bounds__(256, 1) void k_gemm(
    const float* __restrict__ emb, const int* __restrict__ pos,
    const int* __restrict__ sid, const int* __restrict__ role,
    const float* __restrict__ W, const float* __restrict__ bias,
    const float* __restrict__ pe, const float* __restrict__ ide,
    const float* __restrict__ re, float* __restrict__ out) {

    extern __shared__ __align__(16) char dynsm[];
    half*  smh = (half*)dynsm;
    float* smf = (float*)dynsm;

    __shared__ int sTok[128], sPos[128], sSid[128], sRole[128];
    __shared__ int sCnt[SS], sTile[SS + 1];

    int tid = threadIdx.x;
    int wid = tid >> 5, lane = tid & 31;

    if (tid < SS) sCnt[tid] = g_cursor[tid];
    __syncthreads();
    if (tid == 0) {
        int tp = 0;
        for (int s = 0; s < SS; s++) { sTile[s] = tp; tp += (sCnt[s] + 127) >> 7; }
        sTile[SS] = tp;
    }
    __syncthreads();
    int total = sTile[SS] * 8;

    int warp_m = wid & 3;        // 4 warps over M (32 rows each)
    int warp_n = wid >> 2;       // 2 warps over N (64 cols each)
    int row  = tid >> 1;         // load row 0..127
    int colb = (tid & 1) * 16;   // load col base 0 or 16

    for (int t = blockIdx.x; t < total; t += 148) {
        int nt = t & 7, mtl = t >> 3;
        int s = 0;
        while (sTile[s + 1] <= mtl) s++;
        int m0 = (mtl - sTile[s]) << 7;
        int rows = sCnt[s] - m0; if (rows > 128) rows = 128;

        __syncthreads();   // protect sTok + smem reuse from previous tile
        if (tid < 128) {
            int tk = g_tok[s * NT + m0 + ((tid < rows) ? tid : 0)];
            sTok[tid] = tk; sPos[tid] = pos[tk];
            sSid[tid] = sid[tk]; sRole[tid] = role[tk];
        }
        __syncthreads();

        const float* Abase = emb + (size_t)sTok[row] * DD + colb;
        const float* Bbase = W + ((size_t)s * DM + (size_t)nt * 128 + row) * DD + colb;

        // ---- prologue: chunk 0 into stage 0
        float4 ra[4], rb[4];
        #pragma unroll
        for (int q = 0; q < 4; q++) {
            ra[q] = *(const float4*)(Abase + q * 4);
            rb[q] = *(const float4*)(Bbase + q * 4);
        }
        {
            half* Ah = smh;          half* Al = smh + MATH;
            half* Bh = smh + 2 * MATH; half* Bl = smh + 3 * MATH;
            #pragma unroll
            for (int q = 0; q < 4; q++) {
                int off = row * LDH + colb + q * 4;
                split4(ra[q], Ah + off, Al + off);
                split4(rb[q], Bh + off, Bl + off);
            }
        }
        __syncthreads();

        wmma::fragment<wmma::accumulator, 16, 16, 16, float> acc[2][4];
        #pragma unroll
        for (int i = 0; i < 2; i++)
            #pragma unroll
            for (int j = 0; j < 4; j++) wmma::fill_fragment(acc[i][j], 0.0f);

        #pragma unroll 1
        for (int c = 0; c < NCHUNK; c++) {
            if (c < NCHUNK - 1) {
                const float* A2 = Abase + (c + 1) * BK;
                const float* B2 = Bbase + (c + 1) * BK;
                #pragma unroll
                for (int q = 0; q < 4; q++) {
                    ra[q] = *(const float4*)(A2 + q * 4);
                    rb[q] = *(const float4*)(B2 + q * 4);
                }
            }
            const half* Ah = smh + (c & 1) * STAGEH;
            const half* Al = Ah + MATH;
            const half* Bh = Ah + 2 * MATH;
            const half* Bl = Ah + 3 * MATH;

            #pragma unroll
            for (int ks = 0; ks < 2; ks++) {
                wmma::fragment<wmma::matrix_a, 16, 16, 16, half, wmma::row_major> ah[2], al[2];
                wmma::fragment<wmma::matrix_b, 16, 16, 16, half, wmma::col_major> bh[4], bl[4];
                #pragma unroll
                for (int i = 0; i < 2; i++) {
                    const half* pa = Ah + (warp_m * 32 + i * 16) * LDH + ks * 16;
                    const half* qa = Al + (warp_m * 32 + i * 16) * LDH + ks * 16;
                    wmma::load_matrix_sync(ah[i], pa, LDH);
                    wmma::load_matrix_sync(al[i], qa, LDH);
                }
                #pragma unroll
                for (int j = 0; j < 4; j++) {
                    const half* pb = Bh + (warp_n * 64 + j * 16) * LDH + ks * 16;
                    const half* qb = Bl + (warp_n * 64 + j * 16) * LDH + ks * 16;
                    wmma::load_matrix_sync(bh[j], pb, LDH);
                    wmma::load_matrix_sync(bl[j], qb, LDH);
                }
                #pragma unroll
                for (int i = 0; i < 2; i++)
                    #pragma unroll
                    for (int j = 0; j < 4; j++) {
                        wmma::mma_sync(acc[i][j], ah[i], bh[j], acc[i][j]);
                        wmma::mma_sync(acc[i][j], ah[i], bl[j], acc[i][j]);
                        wmma::mma_sync(acc[i][j], al[i], bh[j], acc[i][j]);
                    }
            }

            if (c < NCHUNK - 1) {
                half* An = smh + ((c + 1) & 1) * STAGEH;
                half* Ln = An + MATH;
                half* Bn = An + 2 * MATH;
                half* Mn = An + 3 * MATH;
                #pragma unroll
                for (int q = 0; q < 4; q++) {
                    int off = row * LDH + colb + q * 4;
                    split4(ra[q], An + off, Ln + off);
                    split4(rb[q], Bn + off, Mn + off);
                }
                __syncthreads();
            }
        }

        // ---- epilogue: acc -> smem (reuse stage area), then fused adds + store
        __syncthreads();   // everyone done reading stages
        float* eb = smf + wid * (32 * EPILD);
        #pragma unroll
        for (int i = 0; i < 2; i++)
            #pragma unroll
            for (int j = 0; j < 4; j++)
                wmma::store_matrix_sync(eb + i * 16 * EPILD + j * 16, acc[i][j],
                                        EPILD, wmma::mem_row_major);
        __syncwarp();

        #pragma unroll 1
        for (int it = 0; it < 16; it++) {
            int rr = it * 2 + (lane >> 4);
            int tr = warp_m * 32 + rr;
            if (tr < rows) {
                int c4 = lane & 15;
                int tok = sTok[tr];
                int orow = tok + (tok >> 11) + 1;          // (b,l) -> b*(L+1)+l+1
                int colg4 = nt * 32 + warp_n * 16 + c4;
                float4 v = *(const float4*)(eb + rr * EPILD + c4 * 4);
                float4 bv = ((const float4*)bias)[(size_t)s * 256 + colg4];
                float4 pv = ((const float4*)pe) [(size_t)sPos[tr]  * 256 + colg4];
                float4 iv = ((const float4*)ide)[(size_t)sSid[tr]  * 256 + colg4];
                float4 rv = ((const float4*)re) [(size_t)sRole[tr] * 256 + colg4];
                float4 o;
                o.x = v.x + bv.x + pv.x + iv.x + rv.x;
                o.y = v.y + bv.y + pv.y + iv.y + rv.y;
                o.z = v.z + bv.z + pv.z + iv.z + rv.z;
                o.w = v.w + bv.w + pv.w + iv.w + rv.w;
                ((float4*)out)[(size_t)orow * 256 + colg4] = o;
            }
        }
    }
}

// ---------------------------------------------------------------------------
// kernel_launch
// ---------------------------------------------------------------------------
extern "C" void kernel_launch(void* const* d_in, const int* in_sizes, int n_in,
                              void* d_out, int out_size) {
    const float* emb  = (const float*)d_in[0];
    const int*   pos  = (const int*)d_in[1];
    const int*   sid  = (const int*)d_in[2];
    const int*   role = (const int*)d_in[3];
    const void*  mask = d_in[4];
    const float* pW   = (const float*)d_in[5];
    const float* pb   = (const float*)d_in[6];
    const float* clsc = (const float*)d_in[7];
    const float* pe   = (const float*)d_in[8];
    const float* ide  = (const float*)d_in[9];
    const float* re   = (const float*)d_in[10];
    float* out = (float*)d_out;

    int extra = out_size - TOKELEMS;
    int attnMode = 0;
    if (extra >= NROWS)                attnMode = 1;
    else if (extra >= (NROWS + 3) / 4) attnMode = 2;

    cudaFuncSetAttribute(k_gemm, cudaFuncAttributeMaxDynamicSharedMemorySize, DYN_SMEM);

    k_detect <<<1, 256>>>((const unsigned int*)mask);
    k_scatter<<<NT / 256, 256>>>(sid, mask);
    k_base   <<<NROWS, 256>>>(pos, sid, role, mask, clsc, pe, ide, re, out, attnMode);
    k_gemm   <<<148, 256, DYN_SMEM>>>(emb, pos, sid, role, pW, pb, pe, ide, re, out);
}

// round 9
// speedup vs baseline: 2.4730x; 1.2373x over previous
#include <cuda_runtime.h>
#include <cuda_fp16.h>
#include <mma.h>
#include <cstdint>

using namespace nvcuda;

// ---------------------------------------------------------------------------
// Problem constants
// ---------------------------------------------------------------------------
#define BB   8
#define LL   2048
#define DD   256
#define DM   1024
#define SS   16
#define NT   (BB * LL)
#define LP1  (LL + 1)
#define NROWS (BB * LP1)
#define TOKELEMS (NROWS * DM)

// GEMM tiling
#define BK        32           // fp32 K elements per chunk
#define NCHUNK    (DD / BK)    // 8
#define LDH       40           // halves per row in smem (pad: conflict-free ldmatrix)
#define MATH      (128 * LDH)  // halves per matrix tile (5120)
#define STAGEH    (4 * MATH)   // halves per stage (Ahi,Alo,Bhi,Blo) = 20480
#define EPILD     72           // epilogue smem leading dim (floats)
#define DYN_SMEM  (2 * STAGEH * 2)   // bytes = 81920

// ---------------------------------------------------------------------------
// Device scratch
// ---------------------------------------------------------------------------
__device__ int g_mask_byte;
__device__ int g_cursor[SS];
__device__ int g_tok[SS * NT];

__device__ __forceinline__ bool read_mask(const void* m, int i, int byteMode) {
    if (byteMode) return ((const unsigned char*)m)[i] != 0;
    return ((const unsigned int*)m)[i] != 0u;
}

// ---------------------------------------------------------------------------
// K1: mask layout detect + zero cursors
// ---------------------------------------------------------------------------
__global__ void k_detect(const unsigned int* __restrict__ maskw) {
    __shared__ int bad;
    int tid = threadIdx.x;
    if (tid == 0) bad = 0;
    __syncthreads();
    int mybad = 0;
    for (int i = tid; i < 4096; i += 256) {
        unsigned int v = maskw[i];
        if (v > 1u && v != 0x3F800000u) mybad = 1;
    }
    if (mybad) bad = 1;
    __syncthreads();
    if (tid == 0) g_mask_byte = bad;
    if (tid < SS) g_cursor[tid] = 0;
}

// ---------------------------------------------------------------------------
// K2: bucket tokens into per-signal private regions
// ---------------------------------------------------------------------------
__global__ void k_scatter(const int* __restrict__ sid, const void* __restrict__ mask) {
    __shared__ int cnt[SS], bb[SS];
    int tid = threadIdx.x;
    int t = blockIdx.x * 256 + tid;
    if (tid < SS) cnt[tid] = 0;
    __syncthreads();
    int s = -1, rk = 0;
    if (t < NT && read_mask(mask, t, g_mask_byte)) {
        s = sid[t];
        rk = atomicAdd(&cnt[s], 1);
    }
    __syncthreads();
    if (tid < SS) bb[tid] = cnt[tid] ? atomicAdd(&g_cursor[tid], cnt[tid]) : 0;
    __syncthreads();
    if (s >= 0) g_tok[s * NT + bb[s] + rk] = t;
}

// ---------------------------------------------------------------------------
// K3: base rows (CLS + masked-out) + attn_keep
// ---------------------------------------------------------------------------
__global__ void k_base(const int* __restrict__ pos, const int* __restrict__ sid,
                       const int* __restrict__ role, const void* __restrict__ mask,
                       const float* __restrict__ clsc, const float* __restrict__ pe,
                       const float* __restrict__ ide, const float* __restrict__ re,
                       float* __restrict__ out, int attnMode) {
    int r = blockIdx.x;
    int b = r / LP1;
    int l = r - b * LP1;
    int j = threadIdx.x;
    int t = b * LL + (l - 1);
    bool keep = (l == 0) ? true : read_mask(mask, t, g_mask_byte);

    if (j == 0 && attnMode != 0) {
        if (attnMode == 1) out[(size_t)TOKELEMS + r] = keep ? 1.0f : 0.0f;
        else ((unsigned char*)(out + TOKELEMS))[r] = keep ? 1 : 0;
    }
    if (l > 0 && keep) return;

    const float4* pe4  = (const float4*)pe;
    const float4* ide4 = (const float4*)ide;
    const float4* re4  = (const float4*)re;
    float4 v;
    if (l == 0) {
        float4 c  = ((const float4*)clsc)[j];
        float4 p  = pe4[j];
        float4 id = ide4[(size_t)SS * 256 + j];
        float4 ro = re4[(size_t)2 * 256 + j];
        v.x = c.x + p.x + id.x + ro.x; v.y = c.y + p.y + id.y + ro.y;
        v.z = c.z + p.z + id.z + ro.z; v.w = c.w + p.w + id.w + ro.w;
    } else {
        float4 pv = pe4[(size_t)pos[t] * 256 + j];
        float4 iv = ide4[(size_t)sid[t] * 256 + j];
        float4 rv = re4[(size_t)role[t] * 256 + j];
        v.x = pv.x + iv.x + rv.x; v.y = pv.y + iv.y + rv.y;
        v.z = pv.z + iv.z + rv.z; v.w = pv.w + iv.w + rv.w;
    }
    ((float4*)out)[(size_t)r * 256 + j] = v;
}

// ---------------------------------------------------------------------------
// fp16 hi/lo split store (4 fp32 -> 4 hi halves + 4 lo halves)
// ---------------------------------------------------------------------------
__device__ __forceinline__ void split4(float4 v, half* hp, half* lp) {
    half h0 = __float2half_rn(v.x); half l0 = __float2half_rn(v.x - __half2float(h0));
    half h1 = __float2half_rn(v.y); half l1 = __float2half_rn(v.y - __half2float(h1));
    half h2 = __float2half_rn(v.z); half l2 = __float2half_rn(v.z - __half2float(h2));
    half h3 = __float2half_rn(v.w); half l3 = __float2half_rn(v.w - __half2float(h3));
    *(half2*)(hp)     = __halves2half2(h0, h1);
    *(half2*)(hp + 2) = __halves2half2(h2, h3);
    *(half2*)(lp)     = __halves2half2(l0, l1);
    *(half2*)(lp + 2) = __halves2half2(l2, l3);
}

// ---------------------------------------------------------------------------
// K4: grouped GEMM via wmma (HMMA), 3xFP16 split, fused epilogue.
//     2 CTAs/SM for latency hiding; reduced register pressure.
// ---------------------------------------------------------------------------
__global__ __launch_bounds__(256, 2) void k_gemm(
    const float* __restrict__ emb, const int* __restrict__ pos,
    const int* __restrict__ sid, const int* __restrict__ role,
    const float* __restrict__ W, const float* __restrict__ bias,
    const float* __restrict__ pe, const float* __restrict__ ide,
    const float* __restrict__ re, float* __restrict__ out) {

    extern __shared__ __align__(16) char dynsm[];
    half*  smh = (half*)dynsm;
    float* smf = (float*)dynsm;

    __shared__ int sTok[128], sPos[128], sSid[128], sRole[128];
    __shared__ int sCnt[SS], sTile[SS + 1];

    int tid = threadIdx.x;
    int wid = tid >> 5, lane = tid & 31;

    if (tid < SS) sCnt[tid] = g_cursor[tid];
    __syncthreads();
    if (tid == 0) {
        int tp = 0;
        for (int s = 0; s < SS; s++) { sTile[s] = tp; tp += (sCnt[s] + 127) >> 7; }
        sTile[SS] = tp;
    }
    __syncthreads();
    int total = sTile[SS] * 8;

    int warp_m = wid & 3;        // 4 warps over M (32 rows each)
    int warp_n = wid >> 2;       // 2 warps over N (64 cols each)
    int row  = tid >> 1;         // load row 0..127
    int colb = (tid & 1) * 16;   // load col base 0 or 16

    for (int t = blockIdx.x; t < total; t += 296) {
        int nt = t & 7, mtl = t >> 3;
        int s = 0;
        while (sTile[s + 1] <= mtl) s++;
        int m0 = (mtl - sTile[s]) << 7;
        int rows = sCnt[s] - m0; if (rows > 128) rows = 128;

        __syncthreads();   // protect sTok + smem reuse from previous tile
        if (tid < 128) {
            int tk = g_tok[s * NT + m0 + ((tid < rows) ? tid : 0)];
            sTok[tid] = tk; sPos[tid] = pos[tk];
            sSid[tid] = sid[tk]; sRole[tid] = role[tk];
        }
        __syncthreads();

        const float* Abase = emb + (size_t)sTok[row] * DD + colb;
        const float* Bbase = W + ((size_t)s * DM + (size_t)nt * 128 + row) * DD + colb;

        // ---- prologue: chunk 0 into stage 0
        {
            half* Ah = smh;            half* Al = smh + MATH;
            half* Bh = smh + 2 * MATH; half* Bl = smh + 3 * MATH;
            #pragma unroll
            for (int q = 0; q < 4; q++) {
                float4 a = *(const float4*)(Abase + q * 4);
                float4 b = *(const float4*)(Bbase + q * 4);
                int off = row * LDH + colb + q * 4;
                split4(a, Ah + off, Al + off);
                split4(b, Bh + off, Bl + off);
            }
        }
        __syncthreads();

        wmma::fragment<wmma::accumulator, 16, 16, 16, float> acc[2][4];
        #pragma unroll
        for (int i = 0; i < 2; i++)
            #pragma unroll
            for (int j = 0; j < 4; j++) wmma::fill_fragment(acc[i][j], 0.0f);

        #pragma unroll 1
        for (int c = 0; c < NCHUNK; c++) {
            // Prefetch next chunk's A into registers (latency hidden by MMAs)
            float4 ra[4];
            if (c < NCHUNK - 1) {
                const float* A2 = Abase + (c + 1) * BK;
                #pragma unroll
                for (int q = 0; q < 4; q++) ra[q] = *(const float4*)(A2 + q * 4);
            }
            const half* Ah = smh + (c & 1) * STAGEH;
            const half* Al = Ah + MATH;
            const half* Bh = Ah + 2 * MATH;
            const half* Bl = Ah + 3 * MATH;

            #pragma unroll
            for (int ks = 0; ks < 2; ks++) {
                wmma::fragment<wmma::matrix_a, 16, 16, 16, half, wmma::row_major> ah[2], al[2];
                #pragma unroll
                for (int i = 0; i < 2; i++) {
                    wmma::load_matrix_sync(ah[i], Ah + (warp_m * 32 + i * 16) * LDH + ks * 16, LDH);
                    wmma::load_matrix_sync(al[i], Al + (warp_m * 32 + i * 16) * LDH + ks * 16, LDH);
                }
                #pragma unroll
                for (int j = 0; j < 4; j++) {
                    wmma::fragment<wmma::matrix_b, 16, 16, 16, half, wmma::col_major> bh, bl;
                    wmma::load_matrix_sync(bh, Bh + (warp_n * 64 + j * 16) * LDH + ks * 16, LDH);
                    wmma::load_matrix_sync(bl, Bl + (warp_n * 64 + j * 16) * LDH + ks * 16, LDH);
                    #pragma unroll
                    for (int i = 0; i < 2; i++) {
                        wmma::mma_sync(acc[i][j], ah[i], bh, acc[i][j]);
                        wmma::mma_sync(acc[i][j], ah[i], bl, acc[i][j]);
                        wmma::mma_sync(acc[i][j], al[i], bh, acc[i][j]);
                    }
                }
            }

            if (c < NCHUNK - 1) {
                // Load next B now (hidden by the co-resident CTA's MMA work)
                const float* B2 = Bbase + (c + 1) * BK;
                half* An = smh + ((c + 1) & 1) * STAGEH;
                half* Ln = An + MATH;
                half* Bn = An + 2 * MATH;
                half* Mn = An + 3 * MATH;
                #pragma unroll
                for (int q = 0; q < 4; q++) {
                    float4 b = *(const float4*)(B2 + q * 4);
                    int off = row * LDH + colb + q * 4;
                    split4(ra[q], An + off, Ln + off);
                    split4(b, Bn + off, Mn + off);
                }
                __syncthreads();
            }
        }

        // ---- epilogue: acc -> smem (reuse stage area), then fused adds + store
        __syncthreads();   // everyone done reading stages
        float* eb = smf + wid * (32 * EPILD);
        #pragma unroll
        for (int i = 0; i < 2; i++)
            #pragma unroll
            for (int j = 0; j < 4; j++)
                wmma::store_matrix_sync(eb + i * 16 * EPILD + j * 16, acc[i][j],
                                        EPILD, wmma::mem_row_major);
        __syncwarp();

        #pragma unroll 1
        for (int it = 0; it < 16; it++) {
            int rr = it * 2 + (lane >> 4);
            int tr = warp_m * 32 + rr;
            if (tr < rows) {
                int c4 = lane & 15;
                int tok = sTok[tr];
                int orow = tok + (tok >> 11) + 1;          // (b,l) -> b*(L+1)+l+1
                int colg4 = nt * 32 + warp_n * 16 + c4;
                float4 v = *(const float4*)(eb + rr * EPILD + c4 * 4);
                float4 bv = ((const float4*)bias)[(size_t)s * 256 + colg4];
                float4 pv = ((const float4*)pe) [(size_t)sPos[tr]  * 256 + colg4];
                float4 iv = ((const float4*)ide)[(size_t)sSid[tr]  * 256 + colg4];
                float4 rv = ((const float4*)re) [(size_t)sRole[tr] * 256 + colg4];
                float4 o;
                o.x = v.x + bv.x + pv.x + iv.x + rv.x;
                o.y = v.y + bv.y + pv.y + iv.y + rv.y;
                o.z = v.z + bv.z + pv.z + iv.z + rv.z;
                o.w = v.w + bv.w + pv.w + iv.w + rv.w;
                ((float4*)out)[(size_t)orow * 256 + colg4] = o;
            }
        }
    }
}

// ---------------------------------------------------------------------------
// kernel_launch
// ---------------------------------------------------------------------------
extern "C" void kernel_launch(void* const* d_in, const int* in_sizes, int n_in,
                              void* d_out, int out_size) {
    const float* emb  = (const float*)d_in[0];
    const int*   pos  = (const int*)d_in[1];
    const int*   sid  = (const int*)d_in[2];
    const int*   role = (const int*)d_in[3];
    const void*  mask = d_in[4];
    const float* pW   = (const float*)d_in[5];
    const float* pb   = (const float*)d_in[6];
    const float* clsc = (const float*)d_in[7];
    const float* pe   = (const float*)d_in[8];
    const float* ide  = (const float*)d_in[9];
    const float* re   = (const float*)d_in[10];
    float* out = (float*)d_out;

    int extra = out_size - TOKELEMS;
    int attnMode = 0;
    if (extra >= NROWS)                attnMode = 1;
    else if (extra >= (NROWS + 3) / 4) attnMode = 2;

    cudaFuncSetAttribute(k_gemm, cudaFuncAttributeMaxDynamicSharedMemorySize, DYN_SMEM);

    k_detect <<<1, 256>>>((const unsigned int*)mask);
    k_scatter<<<NT / 256, 256>>>(sid, mask);
    k_base   <<<NROWS, 256>>>(pos, sid, role, mask, clsc, pe, ide, re, out, attnMode);
    k_gemm   <<<296, 256, DYN_SMEM>>>(emb, pos, sid, role, pW, pb, pe, ide, re, out);
}